// round 16
// baseline (speedup 1.0000x reference)
#include <cuda_runtime.h>
#include <cuda_bf16.h>
#include <cstdint>

#define NUM_CH   544     // 32 batches * 17 keypoints
#define HH       256
#define WW       256
#define MAXP     30
#define STRIDE_  4
#define THRESH   0.1f
#define CUT      0.9985f // ~98 threshold-only candidates/channel expected
#define CAP      512
#define THREADS  512
#define RPW      16
#define FULL     0xffffffffu

#define NCTA     592                 // 148 SMs x 4 resident CTAs, all resident
#define NUNIT    (NUM_CH * 4)        // 2176 quarter-channel units (64 KB each)
#define UF4      4096                // float4 per unit

// Per-channel state (zero-initialized at load; selecting CTA resets at end of
// each call -> deterministic across graph replays).
__device__ int   g_cnt [NUM_CH];
__device__ int   g_done[NUM_CH];
__device__ float g_cs  [NUM_CH * CAP];
__device__ int   g_ci  [NUM_CH * CAP];

// Fallback scratch (exact path, never triggered on this input).
__device__ float g_fb_score[(size_t)NUM_CH * 65536];
__device__ int   g_fb_idx  [(size_t)NUM_CH * 65536];

// Fallback: full NMS scan with register pipeline (proven). Keep pixel iff
// v > cut AND v == max of full 3x3 window. Never runs on this input.
static __device__ __noinline__ void scan_pass(const float* __restrict__ chm,
                                              float cut, float* ds, int* di,
                                              int cap, int* cnt)
{
    const int lane = threadIdx.x & 31;
    const int wid  = threadIdx.x >> 5;
    const int r0   = wid * RPW;
    const int c0   = lane * 8;
    const float NI = __int_as_float(0xff800000);

    float P0[8], P1[8], P2[8], vD[8], rmA[8], rmB[8];

    auto LD = [&](int row, float* dst) {
        if ((unsigned)row < HH) {
            const float4 lo = *(const float4*)(chm + row * WW + c0);
            const float4 hi = *(const float4*)(chm + row * WW + c0 + 4);
            dst[0]=lo.x; dst[1]=lo.y; dst[2]=lo.z; dst[3]=lo.w;
            dst[4]=hi.x; dst[5]=hi.y; dst[6]=hi.z; dst[7]=hi.w;
        } else {
            for (int i = 0; i < 8; ++i) dst[i] = NI;
        }
    };

    LD(r0 - 1, P0);
    LD(r0,     P1);
    for (int i = 0; i < 8; ++i) { rmA[i] = NI; rmB[i] = NI; vD[i] = NI; }

    for (int t = 0; t < RPW + 2; ++t) {
        const int rr = r0 - 1 + t;
        if (t <= RPW - 1) {
            LD(rr + 2, P2);
        } else {
            for (int i = 0; i < 8; ++i) P2[i] = NI;
        }
        float lft = __shfl_up_sync(FULL, P0[7], 1);
        if (lane == 0)  lft = NI;
        float rgt = __shfl_down_sync(FULL, P0[0], 1);
        if (lane == 31) rgt = NI;

        float m[7];
        for (int i = 0; i < 7; ++i) m[i] = fmaxf(P0[i], P0[i + 1]);
        float rmC[8];
        rmC[0] = fmaxf(lft, m[0]);
        for (int i = 1; i < 7; ++i) rmC[i] = fmaxf(m[i - 1], P0[i + 1]);
        rmC[7] = fmaxf(m[6], rgt);

        if (t >= 2) {
            const int dr = rr - 1;
            for (int i = 0; i < 8; ++i) {
                const float w = fmaxf(fmaxf(rmA[i], rmB[i]), rmC[i]);
                if (vD[i] > cut && vD[i] == w) {
                    const int p = atomicAdd(cnt, 1);
                    if (p < cap) { ds[p] = vD[i]; di[p] = dr * WW + c0 + i; }
                }
            }
        }
        for (int i = 0; i < 8; ++i) {
            rmA[i] = rmB[i]; rmB[i] = rmC[i];
            vD[i]  = P0[i];  P0[i]  = P1[i]; P1[i] = P2[i];
        }
    }
}

struct Sm {
    float ps[CAP]; int pi[CAP];   // verified peaks (selection scratch)
    int pcount;
    int fcount;
    int sel;
};

// Selection for one channel (runs in the CTA that completed it last).
static __device__ void select_channel(Sm& s, int ch,
                                      const float* __restrict__ hm,
                                      float* __restrict__ out)
{
    const int tid = threadIdx.x;
    const float NI = __int_as_float(0xff800000);
    const float* __restrict__ chm = hm + (size_t)ch * HH * WW;
    float* __restrict__ cs = g_cs + ch * CAP;
    int*   __restrict__ ci = g_ci + ch * CAP;

    const int cnt = g_cnt[ch];
    const bool ok = (cnt <= CAP);
    const int nc  = min(cnt, CAP);

    // 3x3 window check on ~98 candidates (channel is L2-hot: just streamed).
    if (ok) {
        for (int i = tid; i < nc; i += THREADS) {
            const float v  = cs[i];
            const int   id = ci[i];
            const int x = id & (WW - 1);
            const int y = id >> 8;
            const float* rp = chm + id;
            bool peak = true;
            if (x > 0      && __ldg(rp - 1)        > v) peak = false;
            if (x < WW - 1 && __ldg(rp + 1)        > v) peak = false;
            if (y > 0) {
                if (              __ldg(rp - WW)     > v) peak = false;
                if (x > 0      && __ldg(rp - WW - 1) > v) peak = false;
                if (x < WW - 1 && __ldg(rp - WW + 1) > v) peak = false;
            }
            if (y < HH - 1) {
                if (              __ldg(rp + WW)     > v) peak = false;
                if (x > 0      && __ldg(rp + WW - 1) > v) peak = false;
                if (x < WW - 1 && __ldg(rp + WW + 1) > v) peak = false;
            }
            if (peak) {
                const int p = atomicAdd(&s.pcount, 1);   // p < nc <= CAP
                s.ps[p] = v; s.pi[p] = id;
            }
        }
    }
    __syncthreads();

    int n = ok ? s.pcount : 0;
    const float* rs = s.ps;
    const int*   ri = s.pi;

    if (!ok || n < MAXP) {
        // Exact fallback: full NMS at THRESH into global scratch.
        float* gs = g_fb_score + (size_t)ch * 65536;
        int*   gi = g_fb_idx   + (size_t)ch * 65536;
        scan_pass(chm, THRESH, gs, gi, 65536, &s.fcount);
        __syncthreads();
        n = min(s.fcount, 65536);
        rs = gs; ri = gi;
    }

    // Exact rank (score desc, idx asc tiebreak == lax.top_k order).
    for (int i = tid; i < n; i += THREADS) {
        const float sc = rs[i];
        const int   id = ri[i];
        int rank = 0;
        for (int j = 0; j < n; ++j) {
            const float sj = rs[j];
            rank += (sj > sc) || (sj == sc && ri[j] < id);
        }
        if (rank < MAXP) {
            const int x  = id & (WW - 1);
            const int y  = id >> 8;
            const int ob = ch * MAXP + rank;
            out[ob * 2]                 = (float)(x * STRIDE_);
            out[ob * 2 + 1]             = (float)(y * STRIDE_);
            out[NUM_CH * MAXP * 2 + ob] = sc;     // scores segment
            out[NUM_CH * MAXP * 3 + ob] = 1.0f;   // valid segment
        }
    }
    // Padding (never needed on this input; keeps d_out fully written).
    for (int r = n + tid; r < MAXP; r += THREADS) {
        const int ob = ch * MAXP + r;
        out[ob * 2]                 = 0.0f;
        out[ob * 2 + 1]             = 0.0f;
        out[NUM_CH * MAXP * 2 + ob] = NI;
        out[NUM_CH * MAXP * 3 + ob] = 0.0f;
    }

    // Reset per-channel state for the next call / graph replay.
    __syncthreads();
    if (tid == 0) { g_cnt[ch] = 0; g_done[ch] = 0; }
}

__global__ __launch_bounds__(THREADS, 4)
void pose_post_kernel(const float* __restrict__ hm, float* __restrict__ out)
{
    __shared__ Sm s;
    const int tid = threadIdx.x;
    const int bid = blockIdx.x;
    const float4* __restrict__ hm4 = (const float4*)hm;

    // Up to 4 statically-assigned quarter-channel units per CTA.
    #pragma unroll 1
    for (int k = 0; k < 4; ++k) {
        const int unit = bid + k * NCTA;
        if (unit >= NUNIT) break;
        const int ch = unit >> 2;
        const int qr = unit & 3;

        // ---- scan this 64KB unit: 8 coalesced float4/thread, unroll 4 ------
        const float4* __restrict__ up = hm4 + (size_t)unit * UF4;
        float* __restrict__ cs = g_cs + ch * CAP;
        int*   __restrict__ ci = g_ci + ch * CAP;

        #pragma unroll 4
        for (int i = 0; i < 8; ++i) {
            const int q = i * THREADS + tid;
            const float4 v = up[q];
            const float mx = fmaxf(fmaxf(v.x, v.y), fmaxf(v.z, v.w));
            if (mx > CUT) {                       // ~0.6% of float4s
                const int fb = qr * 16384 + q * 4;
                if (v.x > CUT) { int p = atomicAdd(&g_cnt[ch], 1); if (p < CAP) { cs[p] = v.x; ci[p] = fb;     } }
                if (v.y > CUT) { int p = atomicAdd(&g_cnt[ch], 1); if (p < CAP) { cs[p] = v.y; ci[p] = fb + 1; } }
                if (v.z > CUT) { int p = atomicAdd(&g_cnt[ch], 1); if (p < CAP) { cs[p] = v.z; ci[p] = fb + 2; } }
                if (v.w > CUT) { int p = atomicAdd(&g_cnt[ch], 1); if (p < CAP) { cs[p] = v.w; ci[p] = fb + 3; } }
            }
        }

        // ---- release: all threads fence, block-sync, one arrival atomic ----
        __threadfence();
        __syncthreads();
        if (tid == 0) {
            const int old = atomicAdd(&g_done[ch], 1);
            s.sel = (old == 3);
            s.pcount = 0; s.fcount = 0;
        }
        __syncthreads();
        if (s.sel) {
            __threadfence();                     // acquire others' appends
            select_channel(s, ch, hm, out);
            __syncthreads();                     // s reusable for next unit
        }
    }
}

extern "C" void kernel_launch(void* const* d_in, const int* in_sizes, int n_in,
                              void* d_out, int out_size)
{
    const float* hm = (const float*)d_in[0];
    float* out = (float*)d_out;
    pose_post_kernel<<<NCTA, THREADS>>>(hm, out);
}

// round 17
// speedup vs baseline: 2.0399x; 2.0399x over previous
#include <cuda_runtime.h>
#include <cuda_bf16.h>
#include <cstdint>

#define NUM_CH   544     // 32 batches * 17 keypoints
#define HH       256
#define WW       256
#define MAXP     30
#define STRIDE_  4
#define THRESH   0.1f
#define CUT      0.9985f // ~98 threshold-only candidates/channel expected
#define CAP      512
#define THREADS  512
#define RPW      16
#define FULL     0xffffffffu

// Fallback scratch (exact path, never triggered on this input).
__device__ float g_fb_score[(size_t)NUM_CH * 65536];
__device__ int   g_fb_idx  [(size_t)NUM_CH * 65536];

struct Sm {
    float cs[CAP]; int ci[CAP];   // threshold-only candidates
    float ps[CAP]; int pi[CAP];   // verified peaks
    int ccount;
    int pcount;
};

// 256-bit load (Blackwell LDG.E.256): 8 floats per request.
static __device__ __forceinline__ void ldg256(const float* __restrict__ p,
                                              float* r)
{
    asm volatile("ld.global.nc.v8.f32 {%0,%1,%2,%3,%4,%5,%6,%7}, [%8];"
                 : "=f"(r[0]), "=f"(r[1]), "=f"(r[2]), "=f"(r[3]),
                   "=f"(r[4]), "=f"(r[5]), "=f"(r[6]), "=f"(r[7])
                 : "l"(p));
}

// Fallback: full NMS scan with register pipeline (proven). Keep pixel iff
// v > cut AND v == max of full 3x3 window. Never runs on this input.
static __device__ __noinline__ void scan_pass(const float* __restrict__ chm,
                                              float cut, float* ds, int* di,
                                              int cap, int* cnt)
{
    const int lane = threadIdx.x & 31;
    const int wid  = threadIdx.x >> 5;
    const int r0   = wid * RPW;
    const int c0   = lane * 8;
    const float NI = __int_as_float(0xff800000);

    float P0[8], P1[8], P2[8], vD[8], rmA[8], rmB[8];

    auto LD = [&](int row, float* dst) {
        if ((unsigned)row < HH) {
            const float4 lo = *(const float4*)(chm + row * WW + c0);
            const float4 hi = *(const float4*)(chm + row * WW + c0 + 4);
            dst[0]=lo.x; dst[1]=lo.y; dst[2]=lo.z; dst[3]=lo.w;
            dst[4]=hi.x; dst[5]=hi.y; dst[6]=hi.z; dst[7]=hi.w;
        } else {
            for (int i = 0; i < 8; ++i) dst[i] = NI;
        }
    };

    LD(r0 - 1, P0);
    LD(r0,     P1);
    for (int i = 0; i < 8; ++i) { rmA[i] = NI; rmB[i] = NI; vD[i] = NI; }

    for (int t = 0; t < RPW + 2; ++t) {
        const int rr = r0 - 1 + t;
        if (t <= RPW - 1) {
            LD(rr + 2, P2);
        } else {
            for (int i = 0; i < 8; ++i) P2[i] = NI;
        }
        float lft = __shfl_up_sync(FULL, P0[7], 1);
        if (lane == 0)  lft = NI;
        float rgt = __shfl_down_sync(FULL, P0[0], 1);
        if (lane == 31) rgt = NI;

        float m[7];
        for (int i = 0; i < 7; ++i) m[i] = fmaxf(P0[i], P0[i + 1]);
        float rmC[8];
        rmC[0] = fmaxf(lft, m[0]);
        for (int i = 1; i < 7; ++i) rmC[i] = fmaxf(m[i - 1], P0[i + 1]);
        rmC[7] = fmaxf(m[6], rgt);

        if (t >= 2) {
            const int dr = rr - 1;
            for (int i = 0; i < 8; ++i) {
                const float w = fmaxf(fmaxf(rmA[i], rmB[i]), rmC[i]);
                if (vD[i] > cut && vD[i] == w) {
                    const int p = atomicAdd(cnt, 1);
                    if (p < cap) { ds[p] = vD[i]; di[p] = dr * WW + c0 + i; }
                }
            }
        }
        for (int i = 0; i < 8; ++i) {
            rmA[i] = rmB[i]; rmB[i] = rmC[i];
            vD[i]  = P0[i];  P0[i]  = P1[i]; P1[i] = P2[i];
        }
    }
}

__global__ __launch_bounds__(THREADS, 4)
void pose_post_kernel(const float* __restrict__ hm, float* __restrict__ out)
{
    __shared__ Sm s;
    const int tid = threadIdx.x;
    const int ch  = blockIdx.x;
    const float* __restrict__ chm = hm + (size_t)ch * HH * WW;
    const float NI = __int_as_float(0xff800000);

    if (tid == 0) { s.ccount = 0; s.pcount = 0; }
    __syncthreads();

    // ---- Phase A: streaming threshold scan, 256-bit loads ------------------
    // 16 x v8 loads per thread (128 floats), phase-rotated chunk order.
    // Half the memory requests of the float4 version at identical bytes.
    const int wph = ((blockIdx.x * 7) + (tid >> 5) * 5) & 15;

    #pragma unroll 2
    for (int i = 0; i < 16; ++i) {
        const int j = (i + wph) & 15;           // permutation of 0..15
        const int q = j * THREADS + tid;        // v8-granule index
        float r[8];
        ldg256(chm + q * 8, r);
        float mx = r[0];
        #pragma unroll
        for (int e = 1; e < 8; ++e) mx = fmaxf(mx, r[e]);
        if (mx > CUT) {                         // ~1.2% of v8 granules
            const int fb = q * 8;
            #pragma unroll
            for (int e = 0; e < 8; ++e) {
                if (r[e] > CUT) {
                    int p = atomicAdd(&s.ccount, 1);
                    if (p < CAP) { s.cs[p] = r[e]; s.ci[p] = fb + e; }
                }
            }
        }
    }
    __syncthreads();

    const int nc = s.ccount;
    const bool ok = (nc <= CAP);

    // ---- Phase B: 3x3 window check on the ~98 candidates (L2-hot reads) ----
    if (ok) {
        for (int i = tid; i < nc; i += THREADS) {
            const float v  = s.cs[i];
            const int   id = s.ci[i];
            const int x = id & (WW - 1);
            const int y = id >> 8;
            const float* rp = chm + id;
            bool peak = true;
            if (x > 0      && __ldg(rp - 1)        > v) peak = false;
            if (x < WW - 1 && __ldg(rp + 1)        > v) peak = false;
            if (y > 0) {
                if (              __ldg(rp - WW)     > v) peak = false;
                if (x > 0      && __ldg(rp - WW - 1) > v) peak = false;
                if (x < WW - 1 && __ldg(rp - WW + 1) > v) peak = false;
            }
            if (y < HH - 1) {
                if (              __ldg(rp + WW)     > v) peak = false;
                if (x > 0      && __ldg(rp + WW - 1) > v) peak = false;
                if (x < WW - 1 && __ldg(rp + WW + 1) > v) peak = false;
            }
            if (peak) {
                const int p = atomicAdd(&s.pcount, 1);   // p < nc <= CAP
                s.ps[p] = v; s.pi[p] = id;
            }
        }
        __syncthreads();
    }

    int n = ok ? s.pcount : 0;
    const float* rs = s.ps;
    const int*   ri = s.pi;

    if (!ok || n < MAXP) {
        // Exact fallback: full NMS scan at THRESH into global scratch.
        __syncthreads();
        if (tid == 0) s.ccount = 0;
        __syncthreads();
        float* gs = g_fb_score + (size_t)ch * 65536;
        int*   gi = g_fb_idx   + (size_t)ch * 65536;
        scan_pass(chm, THRESH, gs, gi, 65536, &s.ccount);
        __syncthreads();
        n = min(s.ccount, 65536);
        rs = gs; ri = gi;
    }

    // ---- Exact rank (score desc, idx asc tiebreak == lax.top_k order) ------
    for (int i = tid; i < n; i += THREADS) {
        const float sc = rs[i];
        const int   id = ri[i];
        int rank = 0;
        for (int j = 0; j < n; ++j) {
            const float sj = rs[j];
            rank += (sj > sc) || (sj == sc && ri[j] < id);
        }
        if (rank < MAXP) {
            const int x  = id & (WW - 1);
            const int y  = id >> 8;
            const int ob = ch * MAXP + rank;
            out[ob * 2]                 = (float)(x * STRIDE_);
            out[ob * 2 + 1]             = (float)(y * STRIDE_);
            out[NUM_CH * MAXP * 2 + ob] = sc;     // scores segment
            out[NUM_CH * MAXP * 3 + ob] = 1.0f;   // valid segment
        }
    }
    // Padding (never needed on this input; keeps d_out fully written).
    for (int r = n + tid; r < MAXP; r += THREADS) {
        const int ob = ch * MAXP + r;
        out[ob * 2]                 = 0.0f;
        out[ob * 2 + 1]             = 0.0f;
        out[NUM_CH * MAXP * 2 + ob] = NI;
        out[NUM_CH * MAXP * 3 + ob] = 0.0f;
    }
}

extern "C" void kernel_launch(void* const* d_in, const int* in_sizes, int n_in,
                              void* d_out, int out_size)
{
    const float* hm = (const float*)d_in[0];
    float* out = (float*)d_out;
    pose_post_kernel<<<NUM_CH, THREADS>>>(hm, out);
}